// round 17
// baseline (speedup 1.0000x reference)
#include <cuda_runtime.h>
#include <cuda_fp16.h>
#include <math.h>
#include <stdint.h>

// ---------------------------------------------------------------------------
// Problem: x (2,2048,512); W1 (512,2048); W2 (2048,512); HEADS=8
// M = 4096 rows. Output = concat(k, v, out), each 4096*512 fp32.
// R17 (= R15 de-templated): (a) stage-2 GEMM BM=64 (768 CTAs: wave packing);
// (b) prepass merged into ONE kernel. GEMM body identical to R11 best;
// attention = R11 2-buffer version.
// ---------------------------------------------------------------------------
#define MROWS 4096
#define DMODEL 512
#define HID 2048
#define SEQ 2048
#define NHEADS 8
#define DHEAD 64

#define BN 128
#define BKK 32
#define HSTRIDE 40      // gemm smem row stride in halves

// Scratch (device globals: allocation-free rule)
__device__ __align__(16) __half g_hh[3][(size_t)MROWS * HID];     // hidden fp16
__device__ __align__(16) __half g_xh[(size_t)MROWS * DMODEL];     // x fp16
__device__ __align__(16) __half g_w1t[3][(size_t)HID * DMODEL];
__device__ __align__(16) __half g_w2t[3][(size_t)DMODEL * HID];
__device__ __align__(16) __half g_qh[(size_t)MROWS * DMODEL];     // q*0.125 fp16
__device__ __align__(16) __half g_kh[(size_t)MROWS * DMODEL];     // k fp16 copy
__device__ __align__(16) __half g_vh[(size_t)MROWS * DMODEL];     // v fp16 copy

// ----------------------------- helpers -------------------------------------
__device__ __forceinline__ uint32_t smem_u32(const void* p) {
    uint32_t a;
    asm("{ .reg .u64 t; cvta.to.shared.u64 t, %1; cvt.u32.u64 %0, t; }" : "=r"(a) : "l"(p));
    return a;
}
__device__ __forceinline__ void cp16(uint32_t saddr, const void* g) {
    asm volatile("cp.async.cg.shared.global [%0], [%1], 16;" :: "r"(saddr), "l"(g));
}
__device__ __forceinline__ float gelu_f(float x) {
    float x3 = x * x * x;
    float t = tanhf(0.7978845608028654f * (x + 0.044715f * x3));
    return 0.5f * x * (1.0f + t);
}
__device__ __forceinline__ void mma_f16(float* c, const uint32_t* a, const uint32_t* b) {
    asm volatile(
        "mma.sync.aligned.m16n8k16.row.col.f32.f16.f16.f32 "
        "{%0,%1,%2,%3}, {%4,%5,%6,%7}, {%8,%9}, {%0,%1,%2,%3};"
        : "+f"(c[0]), "+f"(c[1]), "+f"(c[2]), "+f"(c[3])
        : "r"(a[0]), "r"(a[1]), "r"(a[2]), "r"(a[3]), "r"(b[0]), "r"(b[1]));
}
__device__ __forceinline__ void ldsm4(uint32_t* r, uint32_t addr) {
    asm volatile("ldmatrix.sync.aligned.m8n8.x4.shared.b16 {%0,%1,%2,%3}, [%4];"
        : "=r"(r[0]), "=r"(r[1]), "=r"(r[2]), "=r"(r[3]) : "r"(addr));
}
__device__ __forceinline__ void ldsm4t(uint32_t* r, uint32_t addr) {
    asm volatile("ldmatrix.sync.aligned.m8n8.x4.trans.shared.b16 {%0,%1,%2,%3}, [%4];"
        : "=r"(r[0]), "=r"(r[1]), "=r"(r[2]), "=r"(r[3]) : "r"(addr));
}
__device__ __forceinline__ uint32_t h2pack(float a, float b) {
    __half2 h = __floats2half2_rn(a, b);
    return *(uint32_t*)&h;
}

// ---------------------------------------------------------------------------
// Merged prepass: ONE launch.
// Blocks [0, 512): convert x to fp16 (1024 float4 per block).
// Blocks [512, 512+6144): 32x32 transpose tiles; which = tile/1024:
//   0..2 -> W1[z] (512x2048 -> 2048x512), 3..5 -> W2[z] (2048x512 -> 512x2048)
// ---------------------------------------------------------------------------
#define XBLOCKS 512
__global__ void __launch_bounds__(256) prepass_all(
    const float* __restrict__ x, __half* __restrict__ xh,
    const float* __restrict__ s10, const float* __restrict__ s11, const float* __restrict__ s12,
    __half* __restrict__ d10, __half* __restrict__ d11, __half* __restrict__ d12,
    const float* __restrict__ s20, const float* __restrict__ s21, const float* __restrict__ s22,
    __half* __restrict__ d20, __half* __restrict__ d21, __half* __restrict__ d22)
{
    __shared__ float tile[32][33];
    const int bx = blockIdx.x;
    if (bx < XBLOCKS) {
        int i0 = bx * 1024 + threadIdx.x;
#pragma unroll
        for (int j = 0; j < 4; j++) {
            int i = i0 + j * 256;
            float4 v = ((const float4*)x)[i];
            __half2 h0 = __floats2half2_rn(v.x, v.y);
            __half2 h1 = __floats2half2_rn(v.z, v.w);
            ((uint2*)xh)[i] = make_uint2(*(uint32_t*)&h0, *(uint32_t*)&h1);
        }
        return;
    }
    const int t = bx - XBLOCKS;
    const int which = t >> 10;
    const int tl = t & 1023;
    const float* src; __half* dst; int R, C, bxt, byt;
    if (which < 3) {
        src = (which == 0) ? s10 : (which == 1) ? s11 : s12;
        dst = (which == 0) ? d10 : (which == 1) ? d11 : d12;
        R = DMODEL; C = HID;
        bxt = tl & 63; byt = tl >> 6;
    } else {
        int w = which - 3;
        src = (w == 0) ? s20 : (w == 1) ? s21 : s22;
        dst = (w == 0) ? d20 : (w == 1) ? d21 : d22;
        R = HID; C = DMODEL;
        bxt = tl & 15; byt = tl >> 4;
    }
    const int tx = threadIdx.x & 31;
    const int ty = threadIdx.x >> 5;
#pragma unroll
    for (int j = 0; j < 4; j++) {
        int r = byt * 32 + ty + j * 8;
        int c = bxt * 32 + tx;
        tile[ty + j * 8][tx] = src[(size_t)r * C + c];
    }
    __syncthreads();
#pragma unroll
    for (int j = 0; j < 4; j++) {
        int dr = bxt * 32 + ty + j * 8;
        int dc = byt * 32 + tx;
        dst[(size_t)dr * R + dc] = __float2half_rn(tile[tx][ty + j * 8]);
    }
}

// ---------------------------------------------------------------------------
// fp16 tensor-core GEMM body (device-inline, MT = warp M-tiles, BM = MT*32).
// 4-stage ring, 8 warps (2Mx4N). out = act(A @ Bt^T + b)
// mode (4 bits): bit0 gelu, bit1 fp32 out, bit2 fp16 out, bit3 *0.125.
// ---------------------------------------------------------------------------
template<int MT>
__device__ __forceinline__ void gemm_body(
    const __half* __restrict__ A, const __half* __restrict__ B,
    const float* __restrict__ bias,
    float* __restrict__ C, __half* __restrict__ H,
    int N, int K, int mode)
{
    extern __shared__ char smem[];
    const uint32_t sb = smem_u32(smem);
    constexpr uint32_t ABUF = (uint32_t)MT * 32 * HSTRIDE * 2;
    constexpr uint32_t BBUF = 128u * HSTRIDE * 2;

    const int tid = threadIdx.x;
    const int wid = tid >> 5;
    const int lane = tid & 31;
    const int bm = blockIdx.y * (MT * 32);
    const int bn = blockIdx.x * BN;
    const int wm = (wid >> 2) * (MT * 16);
    const int wn = (wid & 3) * 32;

    const int lr = lane >> 2;
    const int lc = lane & 3;

    const int grow = tid >> 2;
    const int gchunk = tid & 3;

    uint32_t aOff[MT];
#pragma unroll
    for (int mt = 0; mt < MT; mt++)
        aOff[mt] = (uint32_t)(wm + mt * 16 + (lane & 15)) * (HSTRIDE * 2) + ((lane >> 4) << 4);
    uint32_t bOff[2];
#pragma unroll
    for (int j = 0; j < 2; j++)
        bOff[j] = (uint32_t)(wn + (2 * j + (lane >> 4)) * 8 + (lane & 7)) * (HSTRIDE * 2) + (((lane >> 3) & 1) << 4);

    float acc[MT][4][4];
#pragma unroll
    for (int i = 0; i < MT; i++)
#pragma unroll
        for (int j = 0; j < 4; j++)
#pragma unroll
            for (int t = 0; t < 4; t++) acc[i][j][t] = 0.0f;

    auto loadTile = [&](int kc, int buf) {
#pragma unroll
        for (int j = 0; j < MT / 2; j++) {
            int r = grow + 64 * j;
            cp16(sb + (uint32_t)buf * ABUF + (uint32_t)r * (HSTRIDE * 2) + gchunk * 16,
                 A + (size_t)(bm + r) * K + kc * BKK + gchunk * 8);
        }
#pragma unroll
        for (int j = 0; j < 2; j++) {
            int r = grow + 64 * j;
            cp16(sb + 4 * ABUF + (uint32_t)buf * BBUF + (uint32_t)r * (HSTRIDE * 2) + gchunk * 16,
                 B + (size_t)(bn + r) * K + kc * BKK + gchunk * 8);
        }
        asm volatile("cp.async.commit_group;" ::: "memory");
    };

    const int NC = K / BKK;
    loadTile(0, 0);
    loadTile(1, 1);
    loadTile(2, 2);

    for (int c = 0; c < NC; c++) {
        const int b = c & 3;
        asm volatile("cp.async.wait_group 2;" ::: "memory");
        __syncthreads();
        if (c + 3 < NC) loadTile(c + 3, (c + 3) & 3);
        else asm volatile("cp.async.commit_group;" ::: "memory");

        const uint32_t sA = sb + (uint32_t)b * ABUF;
        const uint32_t sB = sb + 4 * ABUF + (uint32_t)b * BBUF;
#pragma unroll
        for (int kk = 0; kk < 2; kk++) {
            const uint32_t kb = kk * 32;
            uint32_t af[MT][4], bf[4][2];
#pragma unroll
            for (int mt = 0; mt < MT; mt++)
                ldsm4(af[mt], sA + aOff[mt] + kb);
#pragma unroll
            for (int j = 0; j < 2; j++) {
                uint32_t r[4];
                ldsm4(r, sB + bOff[j] + kb);
                bf[2 * j][0] = r[0]; bf[2 * j][1] = r[1];
                bf[2 * j + 1][0] = r[2]; bf[2 * j + 1][1] = r[3];
            }
#pragma unroll
            for (int mt = 0; mt < MT; mt++)
#pragma unroll
                for (int nt = 0; nt < 4; nt++)
                    mma_f16(acc[mt][nt], af[mt], bf[nt]);
        }
    }

    const float scl = (mode & 8) ? 0.125f : 1.0f;
    float2 bv[4];
#pragma unroll
    for (int nt = 0; nt < 4; nt++) {
        int col = bn + wn + nt * 8 + 2 * lc;
        bv[nt] = *(const float2*)(bias + col);
    }
#pragma unroll
    for (int mt = 0; mt < MT; mt++) {
        int row0 = bm + wm + mt * 16 + lr;
#pragma unroll
        for (int nt = 0; nt < 4; nt++) {
            int col = bn + wn + nt * 8 + 2 * lc;
#pragma unroll
            for (int half = 0; half < 2; half++) {
                int row = row0 + half * 8;
                float v0 = acc[mt][nt][2 * half + 0] + bv[nt].x;
                float v1 = acc[mt][nt][2 * half + 1] + bv[nt].y;
                if (mode & 1) { v0 = gelu_f(v0); v1 = gelu_f(v1); }
                v0 *= scl; v1 *= scl;
                if (mode & 2)
                    *(float2*)(C + (size_t)row * N + col) = make_float2(v0, v1);
                if (mode & 4) {
                    __half2 h = __floats2half2_rn(v0, v1);
                    *(__half2*)(H + (size_t)row * N + col) = h;
                }
            }
        }
    }
}

// Plain named kernels (no template globals).
__global__ void __launch_bounds__(256, 2) gemm_mma128(
    const __half* __restrict__ A0, const __half* __restrict__ A1, const __half* __restrict__ A2,
    const __half* __restrict__ B0, const __half* __restrict__ B1, const __half* __restrict__ B2,
    const float* __restrict__ bias0, const float* __restrict__ bias1, const float* __restrict__ bias2,
    float* __restrict__ C0, float* __restrict__ C1, float* __restrict__ C2,
    __half* __restrict__ H0, __half* __restrict__ H1, __half* __restrict__ H2,
    int N, int K, int actModes)
{
    const int z = blockIdx.z;
    const __half* A = (z == 0) ? A0 : (z == 1) ? A1 : A2;
    const __half* B = (z == 0) ? B0 : (z == 1) ? B1 : B2;
    const float* bias = (z == 0) ? bias0 : (z == 1) ? bias1 : bias2;
    float* C = (z == 0) ? C0 : (z == 1) ? C1 : C2;
    __half* H = (z == 0) ? H0 : (z == 1) ? H1 : H2;
    gemm_body<4>(A, B, bias, C, H, N, K, (actModes >> (4 * z)) & 15);
}

__global__ void __launch_bounds__(256, 2) gemm_mma64(
    const __half* __restrict__ A0, const __half* __restrict__ A1, const __half* __restrict__ A2,
    const __half* __restrict__ B0, const __half* __restrict__ B1, const __half* __restrict__ B2,
    const float* __restrict__ bias0, const float* __restrict__ bias1, const float* __restrict__ bias2,
    float* __restrict__ C0, float* __restrict__ C1, float* __restrict__ C2,
    __half* __restrict__ H0, __half* __restrict__ H1, __half* __restrict__ H2,
    int N, int K, int actModes)
{
    const int z = blockIdx.z;
    const __half* A = (z == 0) ? A0 : (z == 1) ? A1 : A2;
    const __half* B = (z == 0) ? B0 : (z == 1) ? B1 : B2;
    const float* bias = (z == 0) ? bias0 : (z == 1) ? bias1 : bias2;
    float* C = (z == 0) ? C0 : (z == 1) ? C1 : C2;
    __half* H = (z == 0) ? H0 : (z == 1) ? H1 : H2;
    gemm_body<2>(A, B, bias, C, H, N, K, (actModes >> (4 * z)) & 15);
}

// ---------------------------------------------------------------------------
// fp16 tensor-core causal flash attention, register-resident P (R11 version).
// ---------------------------------------------------------------------------
#define AQH 0
#define AKH 9216
#define AVH 18432
#define AKVBUF 4608
#define ATTH_BYTES (27648 * 2)

__global__ void __launch_bounds__(256, 2) attention_h(
    const __half* __restrict__ Qg, const __half* __restrict__ Kg,
    const __half* __restrict__ Vg, float* __restrict__ Og)
{
    extern __shared__ __half smh[];
    const uint32_t sb = smem_u32(smh);

    const int tid = threadIdx.x;
    const int wid = tid >> 5;
    const int lane = tid & 31;
    const int lr = lane >> 2;
    const int lc = lane & 3;
    const int qt = gridDim.x - 1 - blockIdx.x;
    const int nb = blockIdx.y >> 3;
    const int h  = blockIdx.y & 7;
    const int bm = qt * 128;
    const int wm = wid * 16;

    const size_t base = ((size_t)nb * SEQ) * DMODEL + (size_t)h * DHEAD;

#pragma unroll
    for (int j = 0; j < 4; j++) {
        int c = tid + 256 * j;
        int r = c >> 3;
        int ch = c & 7;
        cp16(sb + (AQH + r * 72 + ch * 8) * 2, Qg + base + (size_t)(bm + r) * DMODEL + ch * 8);
    }
    asm volatile("cp.async.commit_group;" ::: "memory");

    auto loadKV = [&](int kt, int b) {
#pragma unroll
        for (int j = 0; j < 2; j++) {
            int c = tid + 256 * j;
            int r = c >> 3;
            int ch = c & 7;
            size_t g = base + (size_t)(kt * 64 + r) * DMODEL + ch * 8;
            cp16(sb + (AKH + b * AKVBUF + r * 72 + ch * 8) * 2, Kg + g);
            cp16(sb + (AVH + b * AKVBUF + r * 72 + ch * 8) * 2, Vg + g);
        }
        asm volatile("cp.async.commit_group;" ::: "memory");
    };

    loadKV(0, 0);

    asm volatile("cp.async.wait_group 1;" ::: "memory");
    __syncthreads();
    uint32_t qf[4][4];
    {
        uint32_t qOff = sb + (AQH + (uint32_t)(wm + (lane & 15)) * 72) * 2 + ((lane >> 4) << 4);
#pragma unroll
        for (int ks = 0; ks < 4; ks++)
            ldsm4(qf[ks], qOff + ks * 32);
    }

    uint32_t kOff[4];
#pragma unroll
    for (int j = 0; j < 4; j++)
        kOff[j] = (uint32_t)((2 * j + (lane >> 4)) * 8 + (lane & 7)) * 72 + (((lane >> 3) & 1) << 3);
    uint32_t vOff[4];
#pragma unroll
    for (int j = 0; j < 4; j++)
        vOff[j] = (uint32_t)((((lane >> 3) & 1) << 3) + (lane & 7)) * 72 + 16 * j + ((lane >> 4) << 3);

    float of[8][4];
#pragma unroll
    for (int nf = 0; nf < 8; nf++)
#pragma unroll
        for (int t = 0; t < 4; t++) of[nf][t] = 0.0f;
    float m0 = -1e30f, m1 = -1e30f, l0 = 0.0f, l1 = 0.0f;

    const int r0g = bm + wm + lr;
    const int r1g = r0g + 8;
    const int ntiles = qt * 2 + 2;

    for (int kt = 0; kt < ntiles; kt++) {
        const int b = kt & 1;
        asm volatile("cp.async.wait_group 0;" ::: "memory");
        __syncthreads();
        if (kt + 1 < ntiles) loadKV(kt + 1, b ^ 1);

        const uint32_t sK = sb + (AKH + b * AKVBUF) * 2;
        const uint32_t sV = sb + (AVH + b * AKVBUF) * 2;

        float sf[8][4];
#pragma unroll
        for (int nf = 0; nf < 8; nf++)
#pragma unroll
            for (int t = 0; t < 4; t++) sf[nf][t] = 0.0f;
#pragma unroll
        for (int ks = 0; ks < 4; ks++) {
            uint32_t bf[8][2];
#pragma unroll
            for (int j = 0; j < 4; j++) {
                uint32_t r[4];
                ldsm4(r, sK + kOff[j] * 2 + ks * 32);
                bf[2 * j][0] = r[0]; bf[2 * j][1] = r[1];
                bf[2 * j + 1][0] = r[2]; bf[2 * j + 1][1] = r[3];
            }
#pragma unroll
            for (int nf = 0; nf < 8; nf++)
                mma_f16(sf[nf], qf[ks], bf[nf]);
        }

        if (kt >= ntiles - 2) {
#pragma unroll
            for (int nf = 0; nf < 8; nf++) {
                int c0 = kt * 64 + nf * 8 + 2 * lc;
                if (c0     > r0g) sf[nf][0] = -1e30f;
                if (c0 + 1 > r0g) sf[nf][1] = -1e30f;
                if (c0     > r1g) sf[nf][2] = -1e30f;
                if (c0 + 1 > r1g) sf[nf][3] = -1e30f;
            }
        }

        float mx0 = -1e30f, mx1 = -1e30f;
#pragma unroll
        for (int nf = 0; nf < 8; nf++) {
            mx0 = fmaxf(mx0, fmaxf(sf[nf][0], sf[nf][1]));
            mx1 = fmaxf(mx1, fmaxf(sf[nf][2], sf[nf][3]));
        }
        mx0 = fmaxf(mx0, __shfl_xor_sync(0xffffffffu, mx0, 1));
        mx0 = fmaxf(mx0, __shfl_xor_sync(0xffffffffu, mx0, 2));
        mx1 = fmaxf(mx1, __shfl_xor_sync(0xffffffffu, mx1, 1));
        mx1 = fmaxf(mx1, __shfl_xor_sync(0xffffffffu, mx1, 2));
        float mn0 = fmaxf(m0, mx0), mn1 = fmaxf(m1, mx1);
        float corr0 = __expf(m0 - mn0), corr1 = __expf(m1 - mn1);

        float rs0 = 0.0f, rs1 = 0.0f;
        uint32_t pa[4][4];
#pragma unroll
        for (int nf = 0; nf < 8; nf++) {
            float p0 = __expf(sf[nf][0] - mn0);
            float p1 = __expf(sf[nf][1] - mn0);
            float p2 = __expf(sf[nf][2] - mn1);
            float p3 = __expf(sf[nf][3] - mn1);
            rs0 += p0 + p1;
            rs1 += p2 + p3;
            int ks = nf >> 1;
            int hi = (nf & 1) << 1;
            pa[ks][hi + 0] = h2pack(p0, p1);
            pa[ks][hi + 1] = h2pack(p2, p3);
        }
        rs0 += __shfl_xor_sync(0xffffffffu, rs0, 1);
        rs0 += __shfl_xor_sync(0xffffffffu, rs0, 2);
        rs1 += __shfl_xor_sync(0xffffffffu, rs1, 1);
        rs1 += __shfl_xor_sync(0xffffffffu, rs1, 2);
        l0 = l0 * corr0 + rs0;
        l1 = l1 * corr1 + rs1;
        m0 = mn0; m1 = mn1;
#pragma unroll
        for (int nf = 0; nf < 8; nf++) {
            of[nf][0] *= corr0; of[nf][1] *= corr0;
            of[nf][2] *= corr1; of[nf][3] *= corr1;
        }

#pragma unroll
        for (int ks = 0; ks < 4; ks++) {
            uint32_t bf[8][2];
#pragma unroll
            for (int j = 0; j < 4; j++) {
                uint32_t r[4];
                ldsm4t(r, sV + (vOff[j] + (uint32_t)ks * 16 * 72) * 2);
                bf[2 * j][0] = r[0]; bf[2 * j][1] = r[1];
                bf[2 * j + 1][0] = r[2]; bf[2 * j + 1][1] = r[3];
            }
#pragma unroll
            for (int nf = 0; nf < 8; nf++)
                mma_f16(of[nf], pa[ks], bf[nf]);
        }
    }

    const float inv0 = 1.0f / l0;
    const float inv1 = 1.0f / l1;
#pragma unroll
    for (int nf = 0; nf < 8; nf++) {
        int col = nf * 8 + 2 * lc;
        *(float2*)(Og + base + (size_t)r0g * DMODEL + col) =
            make_float2(of[nf][0] * inv0, of[nf][1] * inv0);
        *(float2*)(Og + base + (size_t)r1g * DMODEL + col) =
            make_float2(of[nf][2] * inv1, of[nf][3] * inv1);
    }
}

// ---------------------------------------------------------------------------
extern "C" void kernel_launch(void* const* d_in, const int* in_sizes, int n_in,
                              void* d_out, int out_size) {
    const float* x   = (const float*)d_in[0];
    const float* qW1 = (const float*)d_in[1];
    const float* qb1 = (const float*)d_in[2];
    const float* qW2 = (const float*)d_in[3];
    const float* qb2 = (const float*)d_in[4];
    const float* kW1 = (const float*)d_in[5];
    const float* kb1 = (const float*)d_in[6];
    const float* kW2 = (const float*)d_in[7];
    const float* kb2 = (const float*)d_in[8];
    const float* vW1 = (const float*)d_in[9];
    const float* vb1 = (const float*)d_in[10];
    const float* vW2 = (const float*)d_in[11];
    const float* vb2 = (const float*)d_in[12];

    float* out = (float*)d_out;
    const size_t seg = (size_t)MROWS * DMODEL;
    float* k_out = out;
    float* v_out = out + seg;
    float* o_out = out + 2 * seg;

    __half *ghh, *gxh, *gw1t, *gw2t, *gqh, *gkh, *gvh;
    cudaGetSymbolAddress((void**)&ghh, g_hh);
    cudaGetSymbolAddress((void**)&gxh, g_xh);
    cudaGetSymbolAddress((void**)&gw1t, g_w1t);
    cudaGetSymbolAddress((void**)&gw2t, g_w2t);
    cudaGetSymbolAddress((void**)&gqh, g_qh);
    cudaGetSymbolAddress((void**)&gkh, g_kh);
    cudaGetSymbolAddress((void**)&gvh, g_vh);
    __half* gh0 = ghh;
    __half* gh1 = ghh + (size_t)MROWS * HID;
    __half* gh2 = ghh + 2 * (size_t)MROWS * HID;
    __half* w1t0 = gw1t;
    __half* w1t1 = gw1t + (size_t)HID * DMODEL;
    __half* w1t2 = gw1t + 2 * (size_t)HID * DMODEL;
    __half* w2t0 = gw2t;
    __half* w2t1 = gw2t + (size_t)DMODEL * HID;
    __half* w2t2 = gw2t + 2 * (size_t)DMODEL * HID;

    cudaFuncSetAttribute(gemm_mma128, cudaFuncAttributeMaxDynamicSharedMemorySize, 81920);
    cudaFuncSetAttribute(gemm_mma64, cudaFuncAttributeMaxDynamicSharedMemorySize, 61440);
    cudaFuncSetAttribute(attention_h, cudaFuncAttributeMaxDynamicSharedMemorySize, ATTH_BYTES);

    // Merged prepass (single launch)
    prepass_all<<<XBLOCKS + 6144, 256>>>(x, gxh,
                                         qW1, kW1, vW1, w1t0, w1t1, w1t2,
                                         qW2, kW2, vW2, w2t0, w2t1, w2t2);

    // Stage 1: hidden[z] = fp16(gelu(x @ W1[z] + b1[z]))  — mode 5 (gelu|fp16)
    {
        dim3 g(HID / BN, MROWS / 128, 3);
        gemm_mma128<<<g, 256, 81920>>>(gxh, gxh, gxh,
                                       w1t0, w1t1, w1t2,
                                       qb1, kb1, vb1,
                                       nullptr, nullptr, nullptr,
                                       gh0, gh1, gh2,
                                       HID, DMODEL, (5) | (5 << 4) | (5 << 8));
    }
    // Stage 2 (BM=64, 768 CTAs): q: fp16*0.125 (12); k: fp32+fp16 (6); v: gelu fp32+fp16 (7)
    {
        dim3 g(DMODEL / BN, MROWS / 64, 3);
        gemm_mma64<<<g, 256, 61440>>>(gh0, gh1, gh2,
                                      w2t0, w2t1, w2t2,
                                      qb2, kb2, vb2,
                                      nullptr, k_out, v_out,
                                      gqh, gkh, gvh,
                                      DMODEL, HID, (12) | (6 << 4) | (7 << 8));
    }
    // Stage 3: attention (fp16 tensor cores, register-resident P)
    {
        dim3 ga(SEQ / 128, 2 * NHEADS);
        attention_h<<<ga, 256, ATTH_BYTES>>>(gqh, gkh, gvh, o_out);
    }
}